// round 9
// baseline (speedup 1.0000x reference)
#include <cuda_runtime.h>
#include <cstdint>

// Problem constants
#define NB    32
#define NH    12
#define GRID  14          // GH == GW
#define LTOK  196         // GRID*GRID
#define DHEAD 64
#define NSTEP 13          // steps 1..13
#define CHUNK 16          // d-chunk per tile (DHEAD/4)
#define TPB   224         // 14 lines x 16 d = 224 tasks, one per thread
#define NBLK  768         // one wave; each block does tiles blk and blk+768

// out[b,h,m,d] = x[b,h,m,d]
//   + sum_{dir,step valid} C[h][dir][step][d] * x[b,h,neighbor(m,dir,step),d]
// C = f(param_1 + param_2).  Separable: ys = x + V(x) in smem, out = ys + H(x).
// Two tiles per block: tile1 = tile0 + 192 bh (same head, same d-quarter) ->
// coefficients shared; tile1's x prefetched via cp.async under tile0's H phase.
//
// Step tables (precomputed, matches reference double-precision build to ~1e-7):
__constant__ float DIST_C[NSTEP] = {
    0.9949110f, 0.9797987f, 0.9551199f, 0.9216104f, 0.8802485f,
    0.8322075f, 0.7788008f, 0.7214223f, 0.6614868f, 0.6003730f,
    0.5393734f, 0.4796523f, 0.4222132f };
__constant__ float FRAC_C[NSTEP] = {
    0.00000000f, 0.23076923f, 0.46153846f, 0.69230769f, 0.92307692f,
    0.15384615f, 0.38461538f, 0.61538462f, 0.84615385f, 0.07692308f,
    0.30769231f, 0.53846154f, 0.76923077f };
__constant__ int SI_C[NSTEP] = { 0,0,0,0,0, 1,1,1,1, 2,2,2,2 };

__device__ __forceinline__ void cp_async16(uint32_t smem_dst, const void* gsrc) {
    asm volatile("cp.async.cg.shared.global [%0], [%1], 16;\n"
                 :: "r"(smem_dst), "l"(gsrc));
}
__device__ __forceinline__ void cp_async_commit() {
    asm volatile("cp.async.commit_group;\n" ::: "memory");
}
__device__ __forceinline__ void cp_async_wait0() {
    asm volatile("cp.async.wait_group 0;\n" ::: "memory");
}

__global__ __launch_bounds__(TPB, 7)
void save_kernel(const float* __restrict__ x,
                 const float* __restrict__ p1,
                 const float* __restrict__ p2,
                 float* __restrict__ out)
{
    __shared__ float xs[LTOK * CHUNK];           // 12544 B : x tile
    __shared__ float ys[LTOK * CHUNK];           // 12544 B : x + V(x)
    __shared__ float Cs[4 * NSTEP * CHUNK];      //  3328 B : per-(head,d) coeffs

    const int blk = blockIdx.x;       // tile0 id; tile1 = blk + NBLK
    const int bh0 = blk >> 2;
    const int dlo = (blk & 3) * CHUNK;
    const int hd  = bh0 % NH;
    const int tid = threadIdx.x;

    const float* xb0 = x   + (size_t)bh0 * (LTOK * DHEAD);
    const float* xb1 = xb0 + (size_t)192 * (LTOK * DHEAD);   // bh0 + 192: same head
    float*       ob0 = out + (size_t)bh0 * (LTOK * DHEAD);
    float*       ob1 = ob0 + (size_t)192 * (LTOK * DHEAD);

    const uint32_t xs_smem = (uint32_t)__cvta_generic_to_shared(xs);

    // ---- tile0 x load via cp.async (overlaps the coeff build below) ----
    #pragma unroll
    for (int it = 0; it < 4; it++) {
        int i = tid + it * TPB;                 // float4 index, 784 total
        if (i < LTOK * (CHUNK / 4)) {
            int row = i >> 2, c4 = i & 3;
            cp_async16(xs_smem + i * 16, xb0 + dlo + row * DHEAD + c4 * 4);
        }
    }
    cp_async_commit();

    // ---- build coefficients Cs[dir][step][d_local] (shared by both tiles) ----
    // param layout: p[(k*DHEAD + d)*NH + h]
    #pragma unroll
    for (int it = 0; it < 4; it++) {
        int i = tid + it * TPB;
        if (i < 4 * NSTEP * CHUNK) {
            int d    = i & (CHUNK - 1);
            int sidx = (i >> 4) % NSTEP;
            int dir  = i / (NSTEP * CHUNK);
            int si   = SI_C[sidx];
            float fr = FRAC_C[sidx];
            float ds = DIST_C[sidx];
            int k0   = dir * 4 + si;
            int ia   = (k0 * DHEAD + dlo + d) * NH + hd;
            int ib   = ((k0 + 1) * DHEAD + dlo + d) * NH + hd;
            float pa = p1[ia] + p2[ia];
            float pb = p1[ib] + p2[ib];
            Cs[i] = ds * (1.0f - fr) * pa + ds * fr * pb;
        }
    }
    cp_async_wait0();
    __syncthreads();

    const int d  = tid & (CHUNK - 1);   // 0..15
    const int g0 = tid >> 4;            // line index 0..13

    #pragma unroll 1
    for (int t = 0; t < 2; t++) {
        float* ob = (t == 0) ? ob0 : ob1;

        // ===== V phase: ys = x + vertical conv (s-outer, interleaved) =====
        {
            const int w = g0;
            float xc[GRID], acc[GRID];
            #pragma unroll
            for (int hh = 0; hh < GRID; hh++) {
                xc[hh]  = xs[(hh * GRID + w) * CHUNK + d];
                acc[hh] = xc[hh];
            }
            #pragma unroll
            for (int s = 1; s <= NSTEP; s++) {
                float c0 = Cs[(0 * NSTEP + (s - 1)) * CHUNK + d];   // top
                float c1 = Cs[(1 * NSTEP + (s - 1)) * CHUNK + d];   // bottom
                #pragma unroll
                for (int hh = s; hh < GRID; hh++)
                    acc[hh] = fmaf(c0, xc[hh - s], acc[hh]);
                #pragma unroll
                for (int hh = 0; hh + s < GRID; hh++)
                    acc[hh] = fmaf(c1, xc[hh + s], acc[hh]);
            }
            #pragma unroll
            for (int hh = 0; hh < GRID; hh++)
                ys[(hh * GRID + w) * CHUNK + d] = acc[hh];
        }
        __syncthreads();   // ys complete before H-phase reads

        // ===== H phase =====
        const int hr = g0;
        float xr[GRID], acc[GRID];
        #pragma unroll
        for (int ww = 0; ww < GRID; ww++) {
            xr[ww]  = xs[(hr * GRID + ww) * CHUNK + d];
            acc[ww] = ys[(hr * GRID + ww) * CHUNK + d];   // x + V already in
        }

        if (t == 0) {
            __syncthreads();   // all warps done reading xs/ys of tile0
            // prefetch tile1's x into xs; completes under H0 compute+stores
            #pragma unroll
            for (int it = 0; it < 4; it++) {
                int i = tid + it * TPB;
                if (i < LTOK * (CHUNK / 4)) {
                    int row = i >> 2, c4 = i & 3;
                    cp_async16(xs_smem + i * 16, xb1 + dlo + row * DHEAD + c4 * 4);
                }
            }
            cp_async_commit();
        }

        #pragma unroll
        for (int s = 1; s <= NSTEP; s++) {
            float c2 = Cs[(2 * NSTEP + (s - 1)) * CHUNK + d];   // left
            float c3 = Cs[(3 * NSTEP + (s - 1)) * CHUNK + d];   // right
            #pragma unroll
            for (int ww = s; ww < GRID; ww++)
                acc[ww] = fmaf(c2, xr[ww - s], acc[ww]);
            #pragma unroll
            for (int ww = 0; ww + s < GRID; ww++)
                acc[ww] = fmaf(c3, xr[ww + s], acc[ww]);
        }
        #pragma unroll
        for (int ww = 0; ww < GRID; ww++)
            ob[(hr * GRID + ww) * DHEAD + dlo + d] = acc[ww];

        if (t == 0) {
            cp_async_wait0();
            __syncthreads();   // tile1 xs ready for next V phase
        }
    }
}

extern "C" void kernel_launch(void* const* d_in, const int* in_sizes, int n_in,
                              void* d_out, int out_size)
{
    // metadata order: x, table, param_1, param_2 (table recomputed analytically)
    const float* x  = (const float*)d_in[0];
    const float* p1 = (const float*)d_in[2];
    const float* p2 = (const float*)d_in[3];
    float*       out = (float*)d_out;

    save_kernel<<<NBLK, TPB>>>(x, p1, p2, out);
}

// round 11
// speedup vs baseline: 1.2098x; 1.2098x over previous
#include <cuda_runtime.h>

// Problem constants
#define NB    32
#define NH    12
#define GRID  14          // GH == GW
#define LTOK  196         // GRID*GRID
#define DHEAD 64
#define NSTEP 13          // steps 1..13
#define CHUNK 16          // d-chunk per block (DHEAD/4)
#define STR   20          // padded token stride (floats): kills 2-way bank conflicts,
                          // 80 B keeps float4 stores 16B-aligned
#define TPB   224         // 14 lines x 16 d = 224 tasks, one per thread

// out[b,h,m,d] = x[b,h,m,d]
//   + sum_{dir,step valid} C[h][dir][step][d] * x[b,h,neighbor(m,dir,step),d]
// C[h][dir][step][d] = sd(step)*P[dir*4+si][d][h] + nd(step)*P[dir*4+si+1][d][h],
// P = param_1 + param_2.  Separable: ys = x + V(x) in smem, out = ys + H(x).
//
// Step tables (precomputed, matches reference double-precision build to ~1e-7):
__constant__ float DIST_C[NSTEP] = {
    0.9949110f, 0.9797987f, 0.9551199f, 0.9216104f, 0.8802485f,
    0.8322075f, 0.7788008f, 0.7214223f, 0.6614868f, 0.6003730f,
    0.5393734f, 0.4796523f, 0.4222132f };
__constant__ float FRAC_C[NSTEP] = {
    0.00000000f, 0.23076923f, 0.46153846f, 0.69230769f, 0.92307692f,
    0.15384615f, 0.38461538f, 0.61538462f, 0.84615385f, 0.07692308f,
    0.30769231f, 0.53846154f, 0.76923077f };
__constant__ int SI_C[NSTEP] = { 0,0,0,0,0, 1,1,1,1, 2,2,2,2 };

__global__ __launch_bounds__(TPB, 6)   // 48-reg budget: keep xc/acc register-resident
void save_kernel(const float* __restrict__ x,
                 const float* __restrict__ p1,
                 const float* __restrict__ p2,
                 float* __restrict__ out)
{
    __shared__ float xs[LTOK * STR];             // 15680 B : x tile (padded)
    __shared__ float ys[LTOK * STR];             // 15680 B : x + V(x) (padded)
    __shared__ float Cs[4 * NSTEP * CHUNK];      //  3328 B : per-(head,d) coeffs

    const int blk = blockIdx.x;       // (b*NH + h) * 4 + dquarter
    const int bh  = blk >> 2;
    const int dlo = (blk & 3) * CHUNK;
    const int hd  = bh % NH;
    const int tid = threadIdx.x;

    const float* xb = x   + (size_t)bh * (LTOK * DHEAD);
    float*       ob = out + (size_t)bh * (LTOK * DHEAD);

    // ---- load x tile (d-quarter) into padded smem, float4-vectorized ----
    // 196 tokens * 4 float4-chunks = 784 vector loads
    #pragma unroll
    for (int it = 0; it < 4; it++) {
        int i = tid + it * TPB;
        if (i < LTOK * (CHUNK / 4)) {
            int row = i >> 2;
            int c4  = i & 3;
            float4 v = *(const float4*)&xb[row * DHEAD + dlo + c4 * 4];
            *(float4*)&xs[row * STR + c4 * 4] = v;    // 80B token stride: aligned
        }
    }

    // ---- build coefficients Cs[dir][step][d_local] ----
    // param layout: p[(k*DHEAD + d)*NH + h]
    #pragma unroll
    for (int it = 0; it < 4; it++) {
        int i = tid + it * TPB;
        if (i < 4 * NSTEP * CHUNK) {
            int d    = i & (CHUNK - 1);
            int sidx = (i >> 4) % NSTEP;
            int dir  = i / (NSTEP * CHUNK);
            int si   = SI_C[sidx];
            float fr = FRAC_C[sidx];
            float ds = DIST_C[sidx];
            int k0   = dir * 4 + si;
            int ia   = (k0 * DHEAD + dlo + d) * NH + hd;
            int ib   = ((k0 + 1) * DHEAD + dlo + d) * NH + hd;
            float pa = p1[ia] + p2[ia];
            float pb = p1[ib] + p2[ib];
            Cs[i] = ds * (1.0f - fr) * pa + ds * fr * pb;
        }
    }
    __syncthreads();

    const int d  = tid & (CHUNK - 1);   // 0..15
    const int g0 = tid >> 4;            // line index 0..13

    // ===== V phase: ys = x + vertical conv (s-outer, interleaved acc) =====
    {
        const int w = g0;

        float xc[GRID], acc[GRID];
        #pragma unroll
        for (int hh = 0; hh < GRID; hh++) {
            xc[hh]  = xs[(hh * GRID + w) * STR + d];
            acc[hh] = xc[hh];
        }
        #pragma unroll
        for (int s = 1; s <= NSTEP; s++) {
            float c0 = Cs[(0 * NSTEP + (s - 1)) * CHUNK + d];   // top    (h - s)
            float c1 = Cs[(1 * NSTEP + (s - 1)) * CHUNK + d];   // bottom (h + s)
            #pragma unroll
            for (int hh = s; hh < GRID; hh++)
                acc[hh] = fmaf(c0, xc[hh - s], acc[hh]);
            #pragma unroll
            for (int hh = 0; hh + s < GRID; hh++)
                acc[hh] = fmaf(c1, xc[hh + s], acc[hh]);
        }
        #pragma unroll
        for (int hh = 0; hh < GRID; hh++)
            ys[(hh * GRID + w) * STR + d] = acc[hh];
    }
    __syncthreads();   // ys complete before H-phase reads

    // ===== H phase: out = ys + horizontal conv (single gmem write) =====
    {
        const int hr = g0;

        float xr[GRID], acc[GRID];
        #pragma unroll
        for (int ww = 0; ww < GRID; ww++) {
            xr[ww]  = xs[(hr * GRID + ww) * STR + d];
            acc[ww] = ys[(hr * GRID + ww) * STR + d];   // x + V already in
        }
        #pragma unroll
        for (int s = 1; s <= NSTEP; s++) {
            float c2 = Cs[(2 * NSTEP + (s - 1)) * CHUNK + d];   // left  (w - s)
            float c3 = Cs[(3 * NSTEP + (s - 1)) * CHUNK + d];   // right (w + s)
            #pragma unroll
            for (int ww = s; ww < GRID; ww++)
                acc[ww] = fmaf(c2, xr[ww - s], acc[ww]);
            #pragma unroll
            for (int ww = 0; ww + s < GRID; ww++)
                acc[ww] = fmaf(c3, xr[ww + s], acc[ww]);
        }
        #pragma unroll
        for (int ww = 0; ww < GRID; ww++)
            ob[(hr * GRID + ww) * DHEAD + dlo + d] = acc[ww];
    }
}

extern "C" void kernel_launch(void* const* d_in, const int* in_sizes, int n_in,
                              void* d_out, int out_size)
{
    // metadata order: x, table, param_1, param_2 (table recomputed analytically)
    const float* x  = (const float*)d_in[0];
    const float* p1 = (const float*)d_in[2];
    const float* p2 = (const float*)d_in[3];
    float*       out = (float*)d_out;

    save_kernel<<<NB * NH * 4, TPB>>>(x, p1, p2, out);
}

// round 13
// speedup vs baseline: 1.2993x; 1.0740x over previous
#include <cuda_runtime.h>

// Problem constants
#define NB    32
#define NH    12
#define GRID  14          // GH == GW
#define LTOK  196         // GRID*GRID
#define DHEAD 64
#define NSTEP 13          // steps 1..13
#define CHUNK 16          // d-chunk per block (DHEAD/4)
#define STR   20          // padded token stride (floats), 16B-aligned, conflict-free
#define TPB   224         // 14 lines x 16 d = 224 tasks, one per thread
#define CSL   (4 * NSTEP * CHUNK)   // 832 coeff floats per (head, d-quarter) slice

// out[b,h,m,d] = x[b,h,m,d]
//   + sum_{dir,step valid} C[h][dir][step][d] * x[b,h,neighbor(m,dir,step),d]
// C[h][dir][step][d] = sd(step)*P[dir*4+si][d][h] + nd(step)*P[dir*4+si+1][d][h],
// P = param_1 + param_2.  Separable: ys = x + V(x) in smem, out = ys + H(x).
//
// Coefficients precomputed once by a prep kernel into Cg (L2-resident);
// main-kernel prologue is fully coalesced (no scattered param loads, no
// per-block coeff arithmetic) -> minimal pre-barrier skew.
//
// Step tables (precomputed, matches reference double-precision build to ~1e-7):
__constant__ float DIST_C[NSTEP] = {
    0.9949110f, 0.9797987f, 0.9551199f, 0.9216104f, 0.8802485f,
    0.8322075f, 0.7788008f, 0.7214223f, 0.6614868f, 0.6003730f,
    0.5393734f, 0.4796523f, 0.4222132f };
__constant__ float FRAC_C[NSTEP] = {
    0.00000000f, 0.23076923f, 0.46153846f, 0.69230769f, 0.92307692f,
    0.15384615f, 0.38461538f, 0.61538462f, 0.84615385f, 0.07692308f,
    0.30769231f, 0.53846154f, 0.76923077f };
__constant__ int SI_C[NSTEP] = { 0,0,0,0,0, 1,1,1,1, 2,2,2,2 };

// Precomputed coefficients: [h][dq][dir][step][d] -> 48 slices x 832 floats
__device__ float Cg[NH * 4 * CSL];   // 159744 B, static device buffer (no alloc)

__global__ __launch_bounds__(CSL, 2)
void prep_kernel(const float* __restrict__ p1, const float* __restrict__ p2)
{
    const int slice = blockIdx.x;        // h*4 + dq
    const int hd    = slice >> 2;
    const int dlo   = (slice & 3) * CHUNK;
    const int i     = threadIdx.x;       // 0..831

    int d    = i & (CHUNK - 1);
    int sidx = (i >> 4) % NSTEP;
    int dir  = i / (NSTEP * CHUNK);
    int si   = SI_C[sidx];
    float fr = FRAC_C[sidx];
    float ds = DIST_C[sidx];
    int k0   = dir * 4 + si;
    int ia   = (k0 * DHEAD + dlo + d) * NH + hd;
    int ib   = ((k0 + 1) * DHEAD + dlo + d) * NH + hd;
    float pa = p1[ia] + p2[ia];
    float pb = p1[ib] + p2[ib];
    Cg[slice * CSL + i] = ds * (1.0f - fr) * pa + ds * fr * pb;
}

__global__ __launch_bounds__(TPB, 6)   // 48-reg budget: xc/acc register-resident
void save_kernel(const float* __restrict__ x, float* __restrict__ out)
{
    __shared__ float xs[LTOK * STR];             // 15680 B : x tile (padded)
    __shared__ float ys[LTOK * STR];             // 15680 B : x + V(x) (padded)
    __shared__ float Cs[CSL];                    //  3328 B : coeff slice

    const int blk = blockIdx.x;       // (b*NH + h) * 4 + dquarter
    const int bh  = blk >> 2;
    const int dlo = (blk & 3) * CHUNK;
    const int hd  = bh % NH;
    const int tid = threadIdx.x;

    const float* xb = x   + (size_t)bh * (LTOK * DHEAD);
    float*       ob = out + (size_t)bh * (LTOK * DHEAD);

    // ---- coalesced coeff-slice load: 208 float4, L2-resident ----
    {
        const float4* cg4 = (const float4*)&Cg[(hd * 4 + (blk & 3)) * CSL];
        if (tid < CSL / 4)
            ((float4*)Cs)[tid] = cg4[tid];
    }

    // ---- load x tile (d-quarter) into padded smem, float4-vectorized ----
    #pragma unroll
    for (int it = 0; it < 4; it++) {
        int i = tid + it * TPB;
        if (i < LTOK * (CHUNK / 4)) {
            int row = i >> 2;
            int c4  = i & 3;
            float4 v = *(const float4*)&xb[row * DHEAD + dlo + c4 * 4];
            *(float4*)&xs[row * STR + c4 * 4] = v;
        }
    }
    __syncthreads();

    const int d  = tid & (CHUNK - 1);   // 0..15
    const int g0 = tid >> 4;            // line index 0..13

    // ===== V phase: ys = x + vertical conv (s-outer, interleaved acc) =====
    {
        const int w = g0;

        float xc[GRID], acc[GRID];
        #pragma unroll
        for (int hh = 0; hh < GRID; hh++) {
            xc[hh]  = xs[(hh * GRID + w) * STR + d];
            acc[hh] = xc[hh];
        }
        #pragma unroll
        for (int s = 1; s <= NSTEP; s++) {
            float c0 = Cs[(0 * NSTEP + (s - 1)) * CHUNK + d];   // top    (h - s)
            float c1 = Cs[(1 * NSTEP + (s - 1)) * CHUNK + d];   // bottom (h + s)
            #pragma unroll
            for (int hh = s; hh < GRID; hh++)
                acc[hh] = fmaf(c0, xc[hh - s], acc[hh]);
            #pragma unroll
            for (int hh = 0; hh + s < GRID; hh++)
                acc[hh] = fmaf(c1, xc[hh + s], acc[hh]);
        }
        #pragma unroll
        for (int hh = 0; hh < GRID; hh++)
            ys[(hh * GRID + w) * STR + d] = acc[hh];
    }
    __syncthreads();   // ys complete before H-phase reads

    // ===== H phase: out = ys + horizontal conv (single gmem write) =====
    {
        const int hr = g0;

        float xr[GRID], acc[GRID];
        #pragma unroll
        for (int ww = 0; ww < GRID; ww++) {
            xr[ww]  = xs[(hr * GRID + ww) * STR + d];
            acc[ww] = ys[(hr * GRID + ww) * STR + d];   // x + V already in
        }
        #pragma unroll
        for (int s = 1; s <= NSTEP; s++) {
            float c2 = Cs[(2 * NSTEP + (s - 1)) * CHUNK + d];   // left  (w - s)
            float c3 = Cs[(3 * NSTEP + (s - 1)) * CHUNK + d];   // right (w + s)
            #pragma unroll
            for (int ww = s; ww < GRID; ww++)
                acc[ww] = fmaf(c2, xr[ww - s], acc[ww]);
            #pragma unroll
            for (int ww = 0; ww + s < GRID; ww++)
                acc[ww] = fmaf(c3, xr[ww + s], acc[ww]);
        }
        #pragma unroll
        for (int ww = 0; ww < GRID; ww++)
            ob[(hr * GRID + ww) * DHEAD + dlo + d] = acc[ww];
    }
}

extern "C" void kernel_launch(void* const* d_in, const int* in_sizes, int n_in,
                              void* d_out, int out_size)
{
    // metadata order: x, table, param_1, param_2 (table recomputed analytically)
    const float* x  = (const float*)d_in[0];
    const float* p1 = (const float*)d_in[2];
    const float* p2 = (const float*)d_in[3];
    float*       out = (float*)d_out;

    prep_kernel<<<NH * 4, CSL>>>(p1, p2);                // coefficients -> Cg
    save_kernel<<<NB * NH * 4, TPB>>>(x, out);           // main pass
}

// round 14
// speedup vs baseline: 1.3345x; 1.0270x over previous
#include <cuda_runtime.h>

// Problem constants
#define NB    32
#define NH    12
#define GRID  14          // GH == GW
#define LTOK  196         // GRID*GRID
#define DHEAD 64
#define NSTEP 13          // steps 1..13
#define CHUNK 16          // d-chunk per block (DHEAD/4)
#define STR   20          // padded token stride (floats), 16B-aligned, conflict-free
#define TPB   224         // 14 lines x 16 d = 224 tasks, one per thread
#define CSL   (4 * NSTEP * CHUNK)   // 832 coeff floats per (head, d-quarter) slice

// out[b,h,m,d] = x[b,h,m,d]
//   + sum_{dir,step valid} C[h][dir][step][d] * x[b,h,neighbor(m,dir,step),d]
// C[h][dir][step][d] = sd(step)*P[dir*4+si][d][h] + nd(step)*P[dir*4+si+1][d][h],
// P = param_1 + param_2.  Separable: ys = x + V(x) in smem, out = ys + H(x).
//
// Coefficients precomputed by a prep kernel into Cg (L2-resident). The save
// kernel is launched with PDL (programmatic stream serialization): it starts
// while prep drains, front-runs its independent x-tile load, and only
// griddepcontrol.wait's before reading Cg -> prep latency hidden.
//
// Step tables (precomputed, matches reference double-precision build to ~1e-7):
__constant__ float DIST_C[NSTEP] = {
    0.9949110f, 0.9797987f, 0.9551199f, 0.9216104f, 0.8802485f,
    0.8322075f, 0.7788008f, 0.7214223f, 0.6614868f, 0.6003730f,
    0.5393734f, 0.4796523f, 0.4222132f };
__constant__ float FRAC_C[NSTEP] = {
    0.00000000f, 0.23076923f, 0.46153846f, 0.69230769f, 0.92307692f,
    0.15384615f, 0.38461538f, 0.61538462f, 0.84615385f, 0.07692308f,
    0.30769231f, 0.53846154f, 0.76923077f };
__constant__ int SI_C[NSTEP] = { 0,0,0,0,0, 1,1,1,1, 2,2,2,2 };

// Precomputed coefficients: [h][dq][dir][step][d] -> 48 slices x 832 floats
__device__ float Cg[NH * 4 * CSL];   // 159744 B, static device buffer (no alloc)

__global__ __launch_bounds__(CSL, 2)
void prep_kernel(const float* __restrict__ p1, const float* __restrict__ p2)
{
    const int slice = blockIdx.x;        // h*4 + dq
    const int hd    = slice >> 2;
    const int dlo   = (slice & 3) * CHUNK;
    const int i     = threadIdx.x;       // 0..831

    int d    = i & (CHUNK - 1);
    int sidx = (i >> 4) % NSTEP;
    int dir  = i / (NSTEP * CHUNK);
    int si   = SI_C[sidx];
    float fr = FRAC_C[sidx];
    float ds = DIST_C[sidx];
    int k0   = dir * 4 + si;
    int ia   = (k0 * DHEAD + dlo + d) * NH + hd;
    int ib   = ((k0 + 1) * DHEAD + dlo + d) * NH + hd;
    float pa = p1[ia] + p2[ia];
    float pb = p1[ib] + p2[ib];
    Cg[slice * CSL + i] = ds * (1.0f - fr) * pa + ds * fr * pb;

    // All Cg writes above are visible to dependents after this trigger.
    asm volatile("griddepcontrol.launch_dependents;" ::: "memory");
}

__global__ __launch_bounds__(TPB, 6)   // 48-reg budget: xc/acc register-resident
void save_kernel(const float* __restrict__ x, float* __restrict__ out)
{
    __shared__ float xs[LTOK * STR];             // 15680 B : x tile (padded)
    __shared__ float ys[LTOK * STR];             // 15680 B : x + V(x) (padded)
    __shared__ float Cs[CSL];                    //  3328 B : coeff slice

    const int blk = blockIdx.x;       // (b*NH + h) * 4 + dquarter
    const int bh  = blk >> 2;
    const int dlo = (blk & 3) * CHUNK;
    const int hd  = bh % NH;
    const int tid = threadIdx.x;

    const float* xb = x   + (size_t)bh * (LTOK * DHEAD);
    float*       ob = out + (size_t)bh * (LTOK * DHEAD);

    // ---- load x tile (d-quarter) into padded smem: INDEPENDENT of prep,
    //      runs before the grid-dependency wait (PDL overlap) ----
    #pragma unroll
    for (int it = 0; it < 4; it++) {
        int i = tid + it * TPB;
        if (i < LTOK * (CHUNK / 4)) {
            int row = i >> 2;
            int c4  = i & 3;
            float4 v = *(const float4*)&xb[row * DHEAD + dlo + c4 * 4];
            *(float4*)&xs[row * STR + c4 * 4] = v;
        }
    }

    // ---- wait for prep's Cg writes, then coalesced coeff-slice load ----
    asm volatile("griddepcontrol.wait;" ::: "memory");
    {
        const float4* cg4 = (const float4*)&Cg[(hd * 4 + (blk & 3)) * CSL];
        if (tid < CSL / 4)
            ((float4*)Cs)[tid] = cg4[tid];
    }
    __syncthreads();

    const int d  = tid & (CHUNK - 1);   // 0..15
    const int g0 = tid >> 4;            // line index 0..13

    // ===== V phase: ys = x + vertical conv (s-outer, interleaved acc) =====
    {
        const int w = g0;

        float xc[GRID], acc[GRID];
        #pragma unroll
        for (int hh = 0; hh < GRID; hh++) {
            xc[hh]  = xs[(hh * GRID + w) * STR + d];
            acc[hh] = xc[hh];
        }
        #pragma unroll
        for (int s = 1; s <= NSTEP; s++) {
            float c0 = Cs[(0 * NSTEP + (s - 1)) * CHUNK + d];   // top    (h - s)
            float c1 = Cs[(1 * NSTEP + (s - 1)) * CHUNK + d];   // bottom (h + s)
            #pragma unroll
            for (int hh = s; hh < GRID; hh++)
                acc[hh] = fmaf(c0, xc[hh - s], acc[hh]);
            #pragma unroll
            for (int hh = 0; hh + s < GRID; hh++)
                acc[hh] = fmaf(c1, xc[hh + s], acc[hh]);
        }
        #pragma unroll
        for (int hh = 0; hh < GRID; hh++)
            ys[(hh * GRID + w) * STR + d] = acc[hh];
    }
    __syncthreads();   // ys complete before H-phase reads

    // ===== H phase: out = ys + horizontal conv (single gmem write) =====
    {
        const int hr = g0;

        float xr[GRID], acc[GRID];
        #pragma unroll
        for (int ww = 0; ww < GRID; ww++) {
            xr[ww]  = xs[(hr * GRID + ww) * STR + d];
            acc[ww] = ys[(hr * GRID + ww) * STR + d];   // x + V already in
        }
        #pragma unroll
        for (int s = 1; s <= NSTEP; s++) {
            float c2 = Cs[(2 * NSTEP + (s - 1)) * CHUNK + d];   // left  (w - s)
            float c3 = Cs[(3 * NSTEP + (s - 1)) * CHUNK + d];   // right (w + s)
            #pragma unroll
            for (int ww = s; ww < GRID; ww++)
                acc[ww] = fmaf(c2, xr[ww - s], acc[ww]);
            #pragma unroll
            for (int ww = 0; ww + s < GRID; ww++)
                acc[ww] = fmaf(c3, xr[ww + s], acc[ww]);
        }
        #pragma unroll
        for (int ww = 0; ww < GRID; ww++)
            ob[(hr * GRID + ww) * DHEAD + dlo + d] = acc[ww];
    }
}

extern "C" void kernel_launch(void* const* d_in, const int* in_sizes, int n_in,
                              void* d_out, int out_size)
{
    // metadata order: x, table, param_1, param_2 (table recomputed analytically)
    const float* x  = (const float*)d_in[0];
    const float* p1 = (const float*)d_in[2];
    const float* p2 = (const float*)d_in[3];
    float*       out = (float*)d_out;

    // 1) coefficients -> Cg
    prep_kernel<<<NH * 4, CSL>>>(p1, p2);

    // 2) main pass, PDL: may begin while prep drains; waits internally for Cg
    cudaLaunchConfig_t cfg = {};
    cfg.gridDim  = dim3(NB * NH * 4);
    cfg.blockDim = dim3(TPB);
    cudaLaunchAttribute attr[1];
    attr[0].id = cudaLaunchAttributeProgrammaticStreamSerialization;
    attr[0].val.programmaticStreamSerializationAllowed = 1;
    cfg.attrs = attr;
    cfg.numAttrs = 1;
    cudaLaunchKernelEx(&cfg, save_kernel, x, out);
}